// round 1
// baseline (speedup 1.0000x reference)
#include <cuda_runtime.h>

// Problem constants (fixed by the reference: H=512, N=64, CH=1, L=2048)
#define HH   512
#define NST  64
#define LFFT 2048
#define NTH  256

__global__ void __launch_bounds__(NTH)
s4d_kernel(const float* __restrict__ lam_re_in, const float* __restrict__ lam_im_in,
           const float* __restrict__ p_re,  const float* __restrict__ p_im,
           const float* __restrict__ b_re,  const float* __restrict__ b_im,
           const float* __restrict__ c_re,  const float* __restrict__ c_im,
           const float* __restrict__ d_in,  const float* __restrict__ log_dt,
           float* __restrict__ out, int write_d)
{
    // Shared layout
    __shared__ float4 a4[NST];      // (lam_re, lam_im, u_re, u_im)
    __shared__ float4 b4[NST];      // (v, w_re, w_im, x_re)
    __shared__ float  sxi[NST];     // x_im
    __shared__ float2 Xb[LFFT];     // FFT ping
    __shared__ float2 Yb[LFFT];     // FFT pong
    __shared__ float2 tw[LFFT/2];   // inverse-FFT twiddles e^{+2pi i j / L}

    const int h   = blockIdx.x;
    const int tid = threadIdx.x;

    // ---- Phase A: per-n invariants (u = conj(P)*B, v = |P|^2, w = conj(C)*B, x = conj(C)*P)
    if (tid < NST) {
        const int idx = h * NST + tid;
        // Lambda = -softplus(Lambda_re) + i*Lambda_im
        float lr = -log1pf(expf(lam_re_in[idx]));
        float li = lam_im_in[idx];
        float pr = p_re[idx], pi = p_im[idx];
        float br = b_re[idx], bi = b_im[idx];
        float cr = c_re[idx], ci = c_im[idx];
        float ur = pr * br + pi * bi;       // conj(P)*B
        float ui = pr * bi - pi * br;
        float v  = pr * pr + pi * pi;       // conj(P)*P (real)
        float wr = cr * br + ci * bi;       // conj(C)*B
        float wi = cr * bi - ci * br;
        float xr = cr * pr + ci * pi;       // conj(C)*P
        float xi = cr * pi - ci * pr;
        a4[tid]  = make_float4(lr, li, ur, ui);
        b4[tid]  = make_float4(v, wr, wi, xr);
        sxi[tid] = xi;
    }
    // inverse-FFT twiddle table: tw[j] = exp(+2*pi*i*j/2048)
    for (int j = tid; j < LFFT / 2; j += NTH) {
        float s, c;
        sincospif(j * (1.0f / 1024.0f), &s, &c);
        tw[j] = make_float2(c, s);
    }
    const float tdt = 2.0f * expf(-log_dt[h]);   // 2/dt
    __syncthreads();

    // ---- Phase B: K_hat[l] for l = tid + k*NTH
    for (int l = tid; l < LFFT; l += NTH) {
        float s, c;
        sincospif(l * (1.0f / 1024.0f), &s, &c);    // angle = 2*pi*l/2048
        const float zr = c, zi = -s;                 // z = exp(-i*angle)
        float denr = 1.0f + zr, deni = zi;
        // eps-clamp exactly like the fp32 reference (|1+z| < eps -> eps)
        if (sqrtf(denr * denr + deni * deni) < 1.1920929e-7f) {
            denr = 1.1920929e-7f; deni = 0.0f;
        }
        const float numr = 1.0f - zr, numi = -zi;
        const float inv  = 1.0f / (denr * denr + deni * deni);
        const float qr = (numr * denr + numi * deni) * inv;   // (1-z)/(1+z)
        const float qi = (numi * denr - numr * deni) * inv;
        const float gr = tdt * qr, gi = tdt * qi;
        const float t2r =  2.0f * denr * inv;                 // 2/(1+z)
        const float t2i = -2.0f * deni * inv;

        float PRBr = 0.f, PRBi = 0.f, PRPr = 0.f, PRPi = 0.f;
        float CRBr = 0.f, CRBi = 0.f, CRPr = 0.f, CRPi = 0.f;
#pragma unroll 8
        for (int n = 0; n < NST; n++) {
            const float4 A = a4[n];
            const float4 B = b4[n];
            const float  xi_ = sxi[n];
            const float dr = gr - A.x;
            const float di = gi - A.y;
            const float rinv = __fdividef(1.0f, dr * dr + di * di);
            const float Rr =  dr * rinv;
            const float Ri = -di * rinv;
            PRBr += A.z * Rr - A.w * Ri;  PRBi += A.z * Ri + A.w * Rr;
            PRPr += B.x * Rr;             PRPi += B.x * Ri;
            CRBr += B.y * Rr - B.z * Ri;  CRBi += B.y * Ri + B.z * Rr;
            CRPr += B.w * Rr - xi_ * Ri;  CRPi += B.w * Ri + xi_ * Rr;
        }
        // Woodbury: f = PRB / (1 + PRP); Khat = (2/(1+z)) * (CRB - CRP*f)
        const float wr_ = 1.0f + PRPr, wi_ = PRPi;
        const float invW = 1.0f / (wr_ * wr_ + wi_ * wi_);
        const float fr = (PRBr * wr_ + PRBi * wi_) * invW;
        const float fi = (PRBi * wr_ - PRBr * wi_) * invW;
        const float er = CRBr - (CRPr * fr - CRPi * fi);
        const float ei = CRBi - (CRPr * fi + CRPi * fr);
        Xb[l] = make_float2(t2r * er - t2i * ei, t2r * ei + t2i * er);
    }

    // ---- Phase C: Stockham radix-2 inverse FFT (self-sorting).
    // 10 general stages ping-pong Xb<->Yb (ends back in Xb), final n=2 stage in place.
    {
        float2* Abuf = Xb;
        float2* Bbuf = Yb;
        int s = 1;
        for (int ncur = LFFT; ncur >= 4; ncur >>= 1, s <<= 1) {
            __syncthreads();
#pragma unroll 4
            for (int k = 0; k < 4; k++) {
                const int bi    = tid + k * NTH;       // [0, 1024)
                const int pbase = bi & ~(s - 1);       // p*s == twiddle index
                const float2 a = Abuf[bi];
                const float2 b = Abuf[bi + LFFT / 2];
                const float2 w = tw[pbase];
                const int o = bi + pbase;
                Bbuf[o] = make_float2(a.x + b.x, a.y + b.y);
                const float sr = a.x - b.x, si = a.y - b.y;
                Bbuf[o + s] = make_float2(sr * w.x - si * w.y, sr * w.y + si * w.x);
            }
            float2* tmp = Abuf; Abuf = Bbuf; Bbuf = tmp;
        }
        // final stage (ncur == 2, s == 1024): in place on Abuf (== Xb)
        __syncthreads();
#pragma unroll 4
        for (int k = 0; k < 4; k++) {
            const int bi = tid + k * NTH;
            const float2 a = Abuf[bi];
            const float2 b = Abuf[bi + LFFT / 2];
            Abuf[bi]            = make_float2(a.x + b.x, a.y + b.y);
            Abuf[bi + LFFT / 2] = make_float2(a.x - b.x, a.y - b.y);
        }
        __syncthreads();

        // ---- Phase D: real part * 1/L -> K[h, :]
        const float scale = 1.0f / (float)LFFT;
        for (int t = tid; t < LFFT; t += NTH)
            out[h * LFFT + t] = Abuf[t].x * scale;
    }

    // ---- D pass-through (CH = 1): out[H*L + h] = D[h]
    if (write_d && tid == 0)
        out[HH * LFFT + h] = d_in[h];
}

extern "C" void kernel_launch(void* const* d_in, const int* in_sizes, int n_in,
                              void* d_out, int out_size)
{
    // metadata order: Lambda_re, Lambda_im, P_re, P_im, B_re, B_im,
    //                 C_re, C_im, D, log_dt, L
    const float* lam_re = (const float*)d_in[0];
    const float* lam_im = (const float*)d_in[1];
    const float* p_re   = (const float*)d_in[2];
    const float* p_im   = (const float*)d_in[3];
    const float* b_re   = (const float*)d_in[4];
    const float* b_im   = (const float*)d_in[5];
    const float* c_re   = (const float*)d_in[6];
    const float* c_im   = (const float*)d_in[7];
    const float* Dv     = (const float*)d_in[8];
    const float* log_dt = (const float*)d_in[9];
    float* out = (float*)d_out;

    const int write_d = (out_size >= HH * LFFT + HH) ? 1 : 0;

    s4d_kernel<<<HH, NTH>>>(lam_re, lam_im, p_re, p_im, b_re, b_im,
                            c_re, c_im, Dv, log_dt, out, write_d);
}

// round 2
// speedup vs baseline: 1.1255x; 1.1255x over previous
#include <cuda_runtime.h>

// Problem constants (fixed by the reference: H=512, N=64, CH=1, L=2048)
#define HH   512
#define NST  64
#define LFFT 2048
#define NF   1024      // half-size complex IFFT length
#define NTH  256

typedef unsigned long long ull;

__device__ __forceinline__ ull pack2(float a, float b) {
    ull r;
    asm("mov.b64 %0, {%1, %2};" : "=l"(r) : "f"(a), "f"(b));
    return r;
}
__device__ __forceinline__ void unpack2(ull v, float& a, float& b) {
    asm("mov.b64 {%0, %1}, %2;" : "=f"(a), "=f"(b) : "l"(v));
}
__device__ __forceinline__ ull ffma2(ull a, ull b, ull c) {
    ull d;
    asm("fma.rn.f32x2 %0, %1, %2, %3;" : "=l"(d) : "l"(a), "l"(b), "l"(c));
    return d;
}
__device__ __forceinline__ float frcp(float x) {
    float r;
    asm("rcp.approx.f32 %0, %1;" : "=f"(r) : "f"(x));
    return r;
}

__global__ void __launch_bounds__(NTH)
s4d_kernel(const float* __restrict__ lam_re_in, const float* __restrict__ lam_im_in,
           const float* __restrict__ p_re,  const float* __restrict__ p_im,
           const float* __restrict__ b_re,  const float* __restrict__ b_im,
           const float* __restrict__ c_re,  const float* __restrict__ c_im,
           const float* __restrict__ d_in,  const float* __restrict__ log_dt,
           float* __restrict__ out, int write_d)
{
    // ---- shared memory ----
    __shared__ float4 cA[NST];      // (dr2, lam_im, v*dr, -v)
    __shared__ float4 cU[NST];      // (ur*dr, ui*dr, ui, -ur)   u = conj(P)*B
    __shared__ float4 cW[NST];      // (wr*dr, wi*dr, wi, -wr)   w = conj(C)*B
    __shared__ float4 cX[NST];      // (xr*dr, xi*dr, xi, -xr)   x = conj(C)*P
    __shared__ float4 rA[NST];      // raw (lam_re, ur, ui, v)   for l==1024 path
    __shared__ float4 rB[NST];      // raw (wr, wi, xr, xi)
    __shared__ float2 Kh[LFFT];     // K_hat; later reused as FFT pong buffer
    __shared__ float2 Cb[NF];       // packed C2R spectrum / FFT ping
    __shared__ float2 tw[NF / 2];   // IFFT-1024 twiddles e^{+2*pi*i*j/1024}

    const int h   = blockIdx.x;
    const int tid = threadIdx.x;

    // ---- Phase A: per-n invariants ----
    if (tid < NST) {
        const int idx = h * NST + tid;
        float lr = -log1pf(expf(lam_re_in[idx]));   // Lambda_re = -softplus
        float li = lam_im_in[idx];
        float pr = p_re[idx], pi = p_im[idx];
        float br = b_re[idx], bi = b_im[idx];
        float cr = c_re[idx], ci = c_im[idx];
        float ur = pr * br + pi * bi;   // conj(P)*B
        float ui = pr * bi - pi * br;
        float v  = pr * pr + pi * pi;   // |P|^2
        float wr = cr * br + ci * bi;   // conj(C)*B
        float wi = cr * bi - ci * br;
        float xr = cr * pr + ci * pi;   // conj(C)*P
        float xi = cr * pi - ci * pr;
        float dr = -lr;                 // g is purely imaginary -> dr = -Lambda_re (l-invariant)
        cA[tid] = make_float4(dr * dr, li, v * dr, -v);
        cU[tid] = make_float4(ur * dr, ui * dr, ui, -ur);
        cW[tid] = make_float4(wr * dr, wi * dr, wi, -wr);
        cX[tid] = make_float4(xr * dr, xi * dr, xi, -xr);
        rA[tid] = make_float4(lr, ur, ui, v);
        rB[tid] = make_float4(wr, wi, xr, xi);
    }
    for (int j = tid; j < NF / 2; j += NTH) {
        float s, c;
        sincospif(j * (1.0f / 512.0f), &s, &c);   // e^{+2*pi*i*j/1024}
        tw[j] = make_float2(c, s);
    }
    const float tdt = 2.0f * expf(-log_dt[h]);    // 2/dt
    __syncthreads();

    // ---- Phase B: K_hat[l] ----
    for (int l = tid; l < LFFT; l += NTH) {
        float er, ei, tau;
        if (l != 1024) {
            float sp, cp;
            sincospif(l * (1.0f / 2048.0f), &sp, &cp);   // theta/2 = pi*l/2048
            tau = __fdividef(sp, cp);                    // tan(theta/2)
            const float gi = tdt * tau;                  // g = i*gi, 2/(1+z) = 1 + i*tau

            ull aU = 0ull, aW = 0ull, aX = 0ull;
            float vr = 0.f, vi = 0.f;
#pragma unroll 8
            for (int n = 0; n < NST; n++) {
                const float4 qa = cA[n];
                const float4 qu = cU[n];
                const float4 qw = cW[n];
                const float4 qx = cX[n];
                const float di  = gi - qa.y;
                const float den = fmaf(di, di, qa.x);
                const float s   = frcp(den);
                const float ds  = di * s;
                const ull s2  = pack2(s, s);
                const ull ds2 = pack2(ds, ds);
                aU = ffma2(pack2(qu.x, qu.y), s2,  aU);
                aU = ffma2(pack2(qu.z, qu.w), ds2, aU);
                aW = ffma2(pack2(qw.x, qw.y), s2,  aW);
                aW = ffma2(pack2(qw.z, qw.w), ds2, aW);
                aX = ffma2(pack2(qx.x, qx.y), s2,  aX);
                aX = ffma2(pack2(qx.z, qx.w), ds2, aX);
                vr = fmaf(qa.z, s,  vr);
                vi = fmaf(qa.w, ds, vi);
            }
            float PRBr, PRBi, CRBr, CRBi, CRPr, CRPi;
            unpack2(aU, PRBr, PRBi);
            unpack2(aW, CRBr, CRBi);
            unpack2(aX, CRPr, CRPi);
            // Woodbury: f = PRB/(1+PRP); e = CRB - CRP*f
            const float wr_ = 1.0f + vr, wi_ = vi;
            const float invW = frcp(fmaf(wr_, wr_, wi_ * wi_));
            const float fr = (PRBr * wr_ + PRBi * wi_) * invW;
            const float fi = (PRBi * wr_ - PRBr * wi_) * invW;
            er = CRBr - (CRPr * fr - CRPi * fi);
            ei = CRBi - (CRPr * fi + CRPi * fr);
            // K_hat = (1 + i*tau) * e
            Kh[l] = make_float2(er - tau * ei, ei + tau * er);
        } else {
            // z = -1 exactly: eps-clamped bin, replicate the reference's fp32 path
            const float EPS = 1.1920929e-7f;
            const float gr = tdt * (2.0f / EPS);   // g = (2/dt)*(1-z)/eps, real
            float PRBr = 0.f, PRBi = 0.f, PRPr = 0.f, PRPi = 0.f;
            float CRBr = 0.f, CRBi = 0.f, CRPr = 0.f, CRPi = 0.f;
            for (int n = 0; n < NST; n++) {
                const float4 a = rA[n];
                const float4 b = rB[n];
                const float lim = cA[n].y;
                const float dr = gr - a.x;
                const float di = -lim;
                const float rinv = 1.0f / fmaf(dr, dr, di * di);
                const float Rr =  dr * rinv;
                const float Ri = -di * rinv;
                PRBr = fmaf(a.y, Rr, PRBr); PRBr = fmaf(-a.z, Ri, PRBr);
                PRBi = fmaf(a.y, Ri, PRBi); PRBi = fmaf( a.z, Rr, PRBi);
                PRPr = fmaf(a.w, Rr, PRPr);
                PRPi = fmaf(a.w, Ri, PRPi);
                CRBr = fmaf(b.x, Rr, CRBr); CRBr = fmaf(-b.y, Ri, CRBr);
                CRBi = fmaf(b.x, Ri, CRBi); CRBi = fmaf( b.y, Rr, CRBi);
                CRPr = fmaf(b.z, Rr, CRPr); CRPr = fmaf(-b.w, Ri, CRPr);
                CRPi = fmaf(b.z, Ri, CRPi); CRPi = fmaf( b.w, Rr, CRPi);
            }
            const float wr_ = 1.0f + PRPr, wi_ = PRPi;
            const float invW = 1.0f / fmaf(wr_, wr_, wi_ * wi_);
            const float fr = (PRBr * wr_ + PRBi * wi_) * invW;
            const float fi = (PRBi * wr_ - PRBr * wi_) * invW;
            er = CRBr - (CRPr * fr - CRPi * fi);
            ei = CRBi - (CRPr * fi + CRPi * fr);
            const float t2 = 2.0f / EPS;           // 2/(1+z) = 2/eps, real
            Kh[l] = make_float2(t2 * er, t2 * ei);
        }
    }
    __syncthreads();

    // ---- Phase C1: Hermitianize + C2R pack into 1024-point spectrum ----
    // Xh[k] = (X[k] + conj(X[(2048-k)%2048]))/2   (Re(ifft(X)) == ifft(Xh))
    // C[k]  = E[k] + O[k],
    //   E = (P + conj(Q) + conj(R) + S)/4,  O = (i/4) e^{i*pi*k/1024} (P + conj(Q) - conj(R) - S)
    //   P = X[k], Q = X[2048-k], R = X[1024-k], S = X[1024+k]
    for (int k = tid; k < NF; k += NTH) {
        const float2 P  = Kh[k];
        const float2 Qv = Kh[(2048 - k) & 2047];
        const float2 Rv = Kh[1024 - k];
        const float2 Sv = Kh[1024 + k];
        const float Er = (P.x + Qv.x + Rv.x + Sv.x) * 0.25f;
        const float Ei = (P.y - Qv.y - Rv.y + Sv.y) * 0.25f;
        const float Dr = (P.x + Qv.x - Rv.x - Sv.x) * 0.25f;
        const float Di = (P.y - Qv.y + Rv.y - Sv.y) * 0.25f;
        float st, ct;
        sincospif(k * (1.0f / 1024.0f), &st, &ct);
        // O = (i e^{i theta}) * D = (-st + i ct) * (Dr + i Di)
        const float Or = -st * Dr - ct * Di;
        const float Oi =  ct * Dr - st * Di;
        Cb[k] = make_float2(Er + Or, Ei + Oi);
    }

    // ---- Phase C2: 1024-point Stockham radix-2 inverse FFT ----
    {
        float2* Abuf = Cb;
        float2* Bbuf = Kh;   // reuse K_hat storage as pong (combine pass is done)
        int s = 1;
        for (int ncur = NF; ncur >= 4; ncur >>= 1, s <<= 1) {   // 9 stages
            __syncthreads();
#pragma unroll 2
            for (int kk = 0; kk < 2; kk++) {
                const int bi    = tid + kk * NTH;        // [0, 512)
                const int pbase = bi & ~(s - 1);
                const float2 a = Abuf[bi];
                const float2 b = Abuf[bi + NF / 2];
                const float2 w = tw[pbase];
                const int o = bi + pbase;
                Bbuf[o] = make_float2(a.x + b.x, a.y + b.y);
                const float sr = a.x - b.x, si = a.y - b.y;
                Bbuf[o + s] = make_float2(sr * w.x - si * w.y, sr * w.y + si * w.x);
            }
            float2* tmp = Abuf; Abuf = Bbuf; Bbuf = tmp;
        }
        // after 9 swaps Abuf == Kh; final stage (ncur=2, s=512) in place
        __syncthreads();
#pragma unroll 2
        for (int kk = 0; kk < 2; kk++) {
            const int bi = tid + kk * NTH;
            const float2 a = Abuf[bi];
            const float2 b = Abuf[bi + NF / 2];
            Abuf[bi]          = make_float2(a.x + b.x, a.y + b.y);
            Abuf[bi + NF / 2] = make_float2(a.x - b.x, a.y - b.y);
        }
        __syncthreads();

        // ---- Phase D: c[n] -> (x[2n], x[2n+1]) with 1/1024 scale ----
        const float sc = 1.0f / (float)NF;
        float2* o2 = (float2*)out;
        for (int n2 = tid; n2 < NF; n2 += NTH) {
            const float2 cv = Abuf[n2];
            o2[h * NF + n2] = make_float2(cv.x * sc, cv.y * sc);
        }
    }

    // ---- D pass-through (CH = 1) ----
    if (write_d && tid == 0)
        out[HH * LFFT + h] = d_in[h];
}

extern "C" void kernel_launch(void* const* d_in, const int* in_sizes, int n_in,
                              void* d_out, int out_size)
{
    const float* lam_re = (const float*)d_in[0];
    const float* lam_im = (const float*)d_in[1];
    const float* p_re   = (const float*)d_in[2];
    const float* p_im   = (const float*)d_in[3];
    const float* b_re   = (const float*)d_in[4];
    const float* b_im   = (const float*)d_in[5];
    const float* c_re   = (const float*)d_in[6];
    const float* c_im   = (const float*)d_in[7];
    const float* Dv     = (const float*)d_in[8];
    const float* log_dt = (const float*)d_in[9];
    float* out = (float*)d_out;

    const int write_d = (out_size >= HH * LFFT + HH) ? 1 : 0;

    s4d_kernel<<<HH, NTH>>>(lam_re, lam_im, p_re, p_im, b_re, b_im,
                            c_re, c_im, Dv, log_dt, out, write_d);
}

// round 3
// speedup vs baseline: 1.2199x; 1.0838x over previous
#include <cuda_runtime.h>

// Problem constants (fixed by the reference: H=512, N=64, CH=1, L=2048)
#define HH   512
#define NST  64
#define LFFT 2048
#define NF   1024      // half-size complex IFFT length
#define NTH  256

typedef unsigned long long ull;

__device__ __forceinline__ ull pack2(float a, float b) {
    ull r;
    asm("mov.b64 %0, {%1, %2};" : "=l"(r) : "f"(a), "f"(b));
    return r;
}
__device__ __forceinline__ void unpack2(ull v, float& a, float& b) {
    asm("mov.b64 {%0, %1}, %2;" : "=f"(a), "=f"(b) : "l"(v));
}
__device__ __forceinline__ ull ffma2(ull a, ull b, ull c) {
    ull d;
    asm("fma.rn.f32x2 %0, %1, %2, %3;" : "=l"(d) : "l"(a), "l"(b), "l"(c));
    return d;
}
__device__ __forceinline__ float frcp(float x) {
    float r;
    asm("rcp.approx.f32 %0, %1;" : "=f"(r) : "f"(x));
    return r;
}

__global__ void __launch_bounds__(NTH, 2)
s4d_kernel(const float* __restrict__ lam_re_in, const float* __restrict__ lam_im_in,
           const float* __restrict__ p_re,  const float* __restrict__ p_im,
           const float* __restrict__ b_re,  const float* __restrict__ b_im,
           const float* __restrict__ c_re,  const float* __restrict__ c_im,
           const float* __restrict__ d_in,  const float* __restrict__ log_dt,
           float* __restrict__ out, int write_d)
{
    // ---- shared memory ----
    // cst[n] (4 x ulonglong2 = 64B per n), pre-packed f32x2 operands:
    //   [0] = { (ur*dr, ui),  (ui*dr, -ur) }    u = conj(P)*B
    //   [1] = { (wr*dr, wi),  (wi*dr, -wr) }    w = conj(C)*B
    //   [2] = { (xr*dr, xi),  (xi*dr, -xr) }    x = conj(C)*P
    //   [3] = { (v*dr, -v),   (dr2, lam_im) }   v = |P|^2
    __shared__ ulonglong2 cst[NST * 4];
    __shared__ float4 rA[NST];      // raw (lam_re, ur, ui, v)   for l==1024 fixup
    __shared__ float4 rB[NST];      // raw (wr, wi, xr, xi)
    __shared__ float2 Kh[LFFT];     // K_hat; later reused as FFT pong buffer
    __shared__ float2 Cb[NF];       // packed C2R spectrum / FFT ping
    __shared__ float2 tw[NF / 2];   // IFFT-1024 twiddles e^{+2*pi*i*j/1024}

    const int h   = blockIdx.x;
    const int tid = threadIdx.x;

    // ---- Phase A: per-n invariants ----
    if (tid < NST) {
        const int idx = h * NST + tid;
        float lr = -log1pf(expf(lam_re_in[idx]));   // Lambda_re = -softplus
        float li = lam_im_in[idx];
        float pr = p_re[idx], pi = p_im[idx];
        float br = b_re[idx], bi = b_im[idx];
        float cr = c_re[idx], ci = c_im[idx];
        float ur = pr * br + pi * bi;   // conj(P)*B
        float ui = pr * bi - pi * br;
        float v  = pr * pr + pi * pi;   // |P|^2
        float wr = cr * br + ci * bi;   // conj(C)*B
        float wi = cr * bi - ci * br;
        float xr = cr * pr + ci * pi;   // conj(C)*P
        float xi = cr * pi - ci * pr;
        float dr = -lr;                 // g purely imaginary -> dr = -Lambda_re (l-invariant)
        cst[tid * 4 + 0] = make_ulonglong2(pack2(ur * dr, ui), pack2(ui * dr, -ur));
        cst[tid * 4 + 1] = make_ulonglong2(pack2(wr * dr, wi), pack2(wi * dr, -wr));
        cst[tid * 4 + 2] = make_ulonglong2(pack2(xr * dr, xi), pack2(xi * dr, -xr));
        cst[tid * 4 + 3] = make_ulonglong2(pack2(v * dr, -v),  pack2(dr * dr, li));
        rA[tid] = make_float4(lr, ur, ui, v);
        rB[tid] = make_float4(wr, wi, xr, xi);
    }
    for (int j = tid; j < NF / 2; j += NTH) {
        float s, c;
        sincospif(j * (1.0f / 512.0f), &s, &c);   // e^{+2*pi*i*j/1024}
        tw[j] = make_float2(c, s);
    }
    const float tdt = 2.0f * expf(-log_dt[h]);    // 2/dt
    __syncthreads();

    // ---- Phase B: K_hat[l], register-blocked 4 l-values per thread ----
    // l = pass*1024 + j*256 + tid.  (l==1024 produces NaN here; fixed up below.)
    for (int pass = 0; pass < 2; pass++) {
        float gi[4], tau[4];
#pragma unroll
        for (int j = 0; j < 4; j++) {
            const int l = pass * 1024 + j * NTH + tid;
            float sp, cp;
            sincospif(l * (1.0f / 2048.0f), &sp, &cp);   // theta/2 = pi*l/2048
            tau[j] = __fdividef(sp, cp);                 // tan(theta/2)
            gi[j]  = tdt * tau[j];                       // g = i*gi
        }
        ull aU1[4], aU2[4], aW1[4], aW2[4], aX1[4], aX2[4], aV[4];
#pragma unroll
        for (int j = 0; j < 4; j++) {
            aU1[j] = aU2[j] = aW1[j] = aW2[j] = aX1[j] = aX2[j] = aV[j] = 0ull;
        }
#pragma unroll 4
        for (int n = 0; n < NST; n++) {
            const ulonglong2 t0 = cst[4 * n + 0];
            const ulonglong2 t1 = cst[4 * n + 1];
            const ulonglong2 t2 = cst[4 * n + 2];
            const ulonglong2 t3 = cst[4 * n + 3];
            float dr2, lam;
            unpack2(t3.y, dr2, lam);
#pragma unroll
            for (int j = 0; j < 4; j++) {
                const float di = gi[j] - lam;
                const float s  = frcp(fmaf(di, di, dr2));
                const float ds = di * s;
                const ull  q   = pack2(s, ds);
                aU1[j] = ffma2(t0.x, q, aU1[j]);
                aU2[j] = ffma2(t0.y, q, aU2[j]);
                aW1[j] = ffma2(t1.x, q, aW1[j]);
                aW2[j] = ffma2(t1.y, q, aW2[j]);
                aX1[j] = ffma2(t2.x, q, aX1[j]);
                aX2[j] = ffma2(t2.y, q, aX2[j]);
                aV[j]  = ffma2(t3.x, q, aV[j]);
            }
        }
        // Epilogue: horizontal adds + Woodbury + K_hat write
#pragma unroll
        for (int j = 0; j < 4; j++) {
            float x0, y0;
            unpack2(aU1[j], x0, y0); const float PRBr = x0 + y0;
            unpack2(aU2[j], x0, y0); const float PRBi = x0 + y0;
            unpack2(aW1[j], x0, y0); const float CRBr = x0 + y0;
            unpack2(aW2[j], x0, y0); const float CRBi = x0 + y0;
            unpack2(aX1[j], x0, y0); const float CRPr = x0 + y0;
            unpack2(aX2[j], x0, y0); const float CRPi = x0 + y0;
            float PRPr, PRPi;
            unpack2(aV[j], PRPr, PRPi);
            const float wr_ = 1.0f + PRPr, wi_ = PRPi;
            const float invW = frcp(fmaf(wr_, wr_, wi_ * wi_));
            const float fr = (PRBr * wr_ + PRBi * wi_) * invW;
            const float fi = (PRBi * wr_ - PRBr * wi_) * invW;
            const float er = CRBr - (CRPr * fr - CRPi * fi);
            const float ei = CRBi - (CRPr * fi + CRPi * fr);
            const int l = pass * 1024 + j * NTH + tid;
            // K_hat = (1 + i*tau) * e
            Kh[l] = make_float2(er - tau[j] * ei, ei + tau[j] * er);
        }
    }

    // ---- l == 1024 fixup (z = -1, eps-clamped bin): exact scalar path ----
    if (tid == 0) {
        const float EPS = 1.1920929e-7f;
        const float gr = tdt * (2.0f / EPS);   // g = (2/dt)*(1-z)/eps, real
        float PRBr = 0.f, PRBi = 0.f, PRPr = 0.f, PRPi = 0.f;
        float CRBr = 0.f, CRBi = 0.f, CRPr = 0.f, CRPi = 0.f;
        for (int n = 0; n < NST; n++) {
            const float4 a = rA[n];
            const float4 b = rB[n];
            float dr2_, lim;
            unpack2(cst[4 * n + 3].y, dr2_, lim);
            const float dr = gr - a.x;
            const float di = -lim;
            const float rinv = 1.0f / fmaf(dr, dr, di * di);
            const float Rr =  dr * rinv;
            const float Ri = -di * rinv;
            PRBr = fmaf(a.y, Rr, PRBr); PRBr = fmaf(-a.z, Ri, PRBr);
            PRBi = fmaf(a.y, Ri, PRBi); PRBi = fmaf( a.z, Rr, PRBi);
            PRPr = fmaf(a.w, Rr, PRPr);
            PRPi = fmaf(a.w, Ri, PRPi);
            CRBr = fmaf(b.x, Rr, CRBr); CRBr = fmaf(-b.y, Ri, CRBr);
            CRBi = fmaf(b.x, Ri, CRBi); CRBi = fmaf( b.y, Rr, CRBi);
            CRPr = fmaf(b.z, Rr, CRPr); CRPr = fmaf(-b.w, Ri, CRPr);
            CRPi = fmaf(b.z, Ri, CRPi); CRPi = fmaf( b.w, Rr, CRPi);
        }
        const float wr_ = 1.0f + PRPr, wi_ = PRPi;
        const float invW = 1.0f / fmaf(wr_, wr_, wi_ * wi_);
        const float fr = (PRBr * wr_ + PRBi * wi_) * invW;
        const float fi = (PRBi * wr_ - PRBr * wi_) * invW;
        const float er = CRBr - (CRPr * fr - CRPi * fi);
        const float ei = CRBi - (CRPr * fi + CRPi * fr);
        const float t2 = 2.0f / EPS;           // 2/(1+z) = 2/eps, real
        Kh[1024] = make_float2(t2 * er, t2 * ei);
    }
    __syncthreads();

    // ---- Phase C1: Hermitianize + C2R pack into 1024-point spectrum ----
    for (int k = tid; k < NF; k += NTH) {
        const float2 P  = Kh[k];
        const float2 Qv = Kh[(2048 - k) & 2047];
        const float2 Rv = Kh[1024 - k];
        const float2 Sv = Kh[1024 + k];
        const float Er = (P.x + Qv.x + Rv.x + Sv.x) * 0.25f;
        const float Ei = (P.y - Qv.y - Rv.y + Sv.y) * 0.25f;
        const float Dr = (P.x + Qv.x - Rv.x - Sv.x) * 0.25f;
        const float Di = (P.y - Qv.y + Rv.y - Sv.y) * 0.25f;
        float st, ct;
        sincospif(k * (1.0f / 1024.0f), &st, &ct);
        // O = (i e^{i theta}) * D
        const float Or = -st * Dr - ct * Di;
        const float Oi =  ct * Dr - st * Di;
        Cb[k] = make_float2(Er + Or, Ei + Oi);
    }

    // ---- Phase C2: 1024-point Stockham radix-2 inverse FFT ----
    {
        float2* Abuf = Cb;
        float2* Bbuf = Kh;   // reuse K_hat storage as pong
        int s = 1;
        for (int ncur = NF; ncur >= 4; ncur >>= 1, s <<= 1) {   // 9 stages
            __syncthreads();
#pragma unroll 2
            for (int kk = 0; kk < 2; kk++) {
                const int bi    = tid + kk * NTH;        // [0, 512)
                const int pbase = bi & ~(s - 1);
                const float2 a = Abuf[bi];
                const float2 b = Abuf[bi + NF / 2];
                const float2 w = tw[pbase];
                const int o = bi + pbase;
                Bbuf[o] = make_float2(a.x + b.x, a.y + b.y);
                const float sr = a.x - b.x, si = a.y - b.y;
                Bbuf[o + s] = make_float2(sr * w.x - si * w.y, sr * w.y + si * w.x);
            }
            float2* tmp = Abuf; Abuf = Bbuf; Bbuf = tmp;
        }
        // after 9 swaps Abuf == Kh; final stage (ncur=2, s=512) in place
        __syncthreads();
#pragma unroll 2
        for (int kk = 0; kk < 2; kk++) {
            const int bi = tid + kk * NTH;
            const float2 a = Abuf[bi];
            const float2 b = Abuf[bi + NF / 2];
            Abuf[bi]          = make_float2(a.x + b.x, a.y + b.y);
            Abuf[bi + NF / 2] = make_float2(a.x - b.x, a.y - b.y);
        }
        __syncthreads();

        // ---- Phase D: c[n] -> (x[2n], x[2n+1]) with 1/1024 scale ----
        const float sc = 1.0f / (float)NF;
        float2* o2 = (float2*)out;
        for (int n2 = tid; n2 < NF; n2 += NTH) {
            const float2 cv = Abuf[n2];
            o2[h * NF + n2] = make_float2(cv.x * sc, cv.y * sc);
        }
    }

    // ---- D pass-through (CH = 1) ----
    if (write_d && tid == 0)
        out[HH * LFFT + h] = d_in[h];
}

extern "C" void kernel_launch(void* const* d_in, const int* in_sizes, int n_in,
                              void* d_out, int out_size)
{
    const float* lam_re = (const float*)d_in[0];
    const float* lam_im = (const float*)d_in[1];
    const float* p_re   = (const float*)d_in[2];
    const float* p_im   = (const float*)d_in[3];
    const float* b_re   = (const float*)d_in[4];
    const float* b_im   = (const float*)d_in[5];
    const float* c_re   = (const float*)d_in[6];
    const float* c_im   = (const float*)d_in[7];
    const float* Dv     = (const float*)d_in[8];
    const float* log_dt = (const float*)d_in[9];
    float* out = (float*)d_out;

    const int write_d = (out_size >= HH * LFFT + HH) ? 1 : 0;

    s4d_kernel<<<HH, NTH>>>(lam_re, lam_im, p_re, p_im, b_re, b_im,
                            c_re, c_im, Dv, log_dt, out, write_d);
}